// round 1
// baseline (speedup 1.0000x reference)
#include <cuda_runtime.h>
#include <math.h>

// Problem constants
#define Bb 4
#define Ss 2048
#define Dd 768
#define Hh 12
#define Ff 3072
#define Ll 4
#define DHh 64
#define Mrows (Bb*Ss)   // 8192

// Scratch (device globals; allocation is forbidden)
__device__ float g_x[Bb*Ss*Dd];     // running activations (h)
__device__ float g_q[Bb*Ss*Dd];     // q / attn_out scratch
__device__ float g_k[Bb*Ss*Dd];
__device__ float g_v[Bb*Ss*Dd];
__device__ float g_attn[Bb*Ss*Dd];  // av merged / ffn out
__device__ float g_mid[Bb*Ss*Ff];   // ffn intermediate

// ----------------------------------------------------------------------------
// SGEMM: C[M,N] = A[M,K] @ B[K,N] (+bias over cols) (+exact GELU if ACT==1)
// BM=BN=64, BK=16, 256 threads, 4x4 per-thread microtile.
// ----------------------------------------------------------------------------
template<int ACT>
__global__ void __launch_bounds__(256) sgemm_kernel(
    const float* __restrict__ A, const float* __restrict__ Bm,
    const float* __restrict__ bias, float* __restrict__ C,
    int M, int N, int K)
{
    __shared__ float As[16][64];   // [k][m]
    __shared__ float Bs[16][64];   // [k][n]

    const int t  = threadIdx.x;
    const int tx = t & 15;         // 0..15 -> col group
    const int ty = t >> 4;         // 0..15 -> row group
    const int row0 = blockIdx.y * 64;
    const int col0 = blockIdx.x * 64;

    // A tile loader: thread loads float4 at (ar, ak..ak+3)
    const int ar = t >> 2;
    const int ak = (t & 3) * 4;
    // B tile loader: thread loads float4 at (bk, bn..bn+3)
    const int bk = t >> 4;
    const int bn = (t & 15) * 4;

    const float* Aptr = A + (size_t)(row0 + ar) * K + ak;
    const float* Bptr = Bm + (size_t)bk * N + col0 + bn;

    float acc[4][4];
    #pragma unroll
    for (int i = 0; i < 4; i++)
        #pragma unroll
        for (int j = 0; j < 4; j++) acc[i][j] = 0.f;

    for (int k0 = 0; k0 < K; k0 += 16) {
        float4 av = *(const float4*)Aptr;
        float4 bv = *(const float4*)Bptr;
        As[ak + 0][ar] = av.x;
        As[ak + 1][ar] = av.y;
        As[ak + 2][ar] = av.z;
        As[ak + 3][ar] = av.w;
        *(float4*)&Bs[bk][bn] = bv;
        __syncthreads();

        #pragma unroll
        for (int kk = 0; kk < 16; kk++) {
            float4 a4 = *(const float4*)&As[kk][ty * 4];
            float4 b4 = *(const float4*)&Bs[kk][tx * 4];
            float a[4] = {a4.x, a4.y, a4.z, a4.w};
            float b[4] = {b4.x, b4.y, b4.z, b4.w};
            #pragma unroll
            for (int i = 0; i < 4; i++)
                #pragma unroll
                for (int j = 0; j < 4; j++)
                    acc[i][j] = fmaf(a[i], b[j], acc[i][j]);
        }
        __syncthreads();

        Aptr += 16;
        Bptr += (size_t)16 * N;
    }

    const int crow = row0 + ty * 4;
    const int ccol = col0 + tx * 4;
    #pragma unroll
    for (int i = 0; i < 4; i++) {
        float4 o;
        float* po = (float*)&o;
        #pragma unroll
        for (int j = 0; j < 4; j++) {
            float v = acc[i][j];
            if (bias) v += bias[ccol + j];
            if (ACT == 1) {
                // exact GELU: x * 0.5 * (1 + erf(x / sqrt(2)))
                v = 0.5f * v * (1.0f + erff(v * 0.70710678118654752f));
            }
            po[j] = v;
        }
        *(float4*)&C[(size_t)(crow + i) * N + ccol] = o;
    }
}

// ----------------------------------------------------------------------------
// Flash attention (causal), fp32, one 64-row Q tile per block, 256 threads.
// Layouts: Q/K/V/O are merged (B,S,D) with head h at columns [h*64, h*64+64).
// Smem rows padded to 68 floats: all LDS patterns bank-conflict-free.
// Thread t: query row r = t>>2; score keys {kq + 4*kk} (kq = t&3, strided);
//           output dims [cg, cg+16) (cg = (t&3)*16, contiguous for float4).
// ----------------------------------------------------------------------------
#define FLASH_LD 68
#define FLASH_SMEM (3 * 64 * FLASH_LD * 4)

__global__ void __launch_bounds__(256) flash_attn_kernel(
    const float* __restrict__ Q, const float* __restrict__ Kt,
    const float* __restrict__ Vt, float* __restrict__ O)
{
    extern __shared__ float sm[];
    float* Qs = sm;                       // 64 x 68
    float* Ks = sm + 64 * FLASH_LD;       // 64 x 68, reused as P after scores
    float* Vs = sm + 2 * 64 * FLASH_LD;   // 64 x 68

    const int qt = blockIdx.x;            // query tile 0..31
    const int bh = blockIdx.y;            // b*H + h
    const int b  = bh / Hh;
    const int h  = bh % Hh;
    const int t  = threadIdx.x;
    const int r  = t >> 2;                // query row 0..63
    const int kq = t & 3;                 // key sub-lane
    const int cg = (t & 3) * 16;          // output dim group

    const size_t base = (size_t)b * Ss * Dd + (size_t)h * DHh;

    // Load Q tile (64 rows x 64 dims)
    for (int idx = t; idx < 64 * 16; idx += 256) {
        int i  = idx >> 4;
        int dq = (idx & 15) * 4;
        *(float4*)&Qs[i * FLASH_LD + dq] =
            *(const float4*)(Q + base + (size_t)(qt * 64 + i) * Dd + dq);
    }

    float m = -1e30f, l = 0.f;
    float acc[16];
    #pragma unroll
    for (int i = 0; i < 16; i++) acc[i] = 0.f;

    for (int jt = 0; jt <= qt; jt++) {
        __syncthreads();  // previous iteration's P/V readers done
        for (int idx = t; idx < 64 * 16; idx += 256) {
            int i  = idx >> 4;
            int dq = (idx & 15) * 4;
            *(float4*)&Ks[i * FLASH_LD + dq] =
                *(const float4*)(Kt + base + (size_t)(jt * 64 + i) * Dd + dq);
            *(float4*)&Vs[i * FLASH_LD + dq] =
                *(const float4*)(Vt + base + (size_t)(jt * 64 + i) * Dd + dq);
        }
        __syncthreads();

        // scores: s[kk] = Q[r] . K[kq + 4*kk]
        float s[16];
        #pragma unroll
        for (int kk = 0; kk < 16; kk++) s[kk] = 0.f;
        #pragma unroll 4
        for (int d4 = 0; d4 < 64; d4 += 4) {
            float4 q4 = *(const float4*)&Qs[r * FLASH_LD + d4];
            #pragma unroll
            for (int kk = 0; kk < 16; kk++) {
                float4 k4 = *(const float4*)&Ks[(kq + 4 * kk) * FLASH_LD + d4];
                s[kk] = fmaf(q4.x, k4.x,
                        fmaf(q4.y, k4.y,
                        fmaf(q4.z, k4.z,
                        fmaf(q4.w, k4.w, s[kk]))));
            }
        }

        // scale + causal mask + tile max
        float mloc = -1e30f;
        const bool diag = (jt == qt);
        #pragma unroll
        for (int kk = 0; kk < 16; kk++) {
            float sv = s[kk] * 0.125f;
            if (diag && (kq + 4 * kk) > r) sv = -1e9f;
            s[kk] = sv;
            mloc = fmaxf(mloc, sv);
        }
        mloc = fmaxf(mloc, __shfl_xor_sync(0xffffffffu, mloc, 1));
        mloc = fmaxf(mloc, __shfl_xor_sync(0xffffffffu, mloc, 2));

        const float mnew  = fmaxf(m, mloc);
        const float scale = __expf(m - mnew);

        float lloc = 0.f;
        #pragma unroll
        for (int kk = 0; kk < 16; kk++) {
            s[kk] = __expf(s[kk] - mnew);
            lloc += s[kk];
        }
        lloc += __shfl_xor_sync(0xffffffffu, lloc, 1);
        lloc += __shfl_xor_sync(0xffffffffu, lloc, 2);
        l = l * scale + lloc;
        m = mnew;
        #pragma unroll
        for (int i = 0; i < 16; i++) acc[i] *= scale;

        __syncthreads();  // all score readers of Ks done before overwrite with P
        #pragma unroll
        for (int kk = 0; kk < 16; kk++)
            Ks[r * FLASH_LD + kq + 4 * kk] = s[kk];
        __syncthreads();

        // acc[d] += sum_j P[r][j] * V[j][cg + d]
        #pragma unroll 8
        for (int j = 0; j < 64; j++) {
            float pj = Ks[r * FLASH_LD + j];
            const float* vrow = &Vs[j * FLASH_LD + cg];
            float4 v0 = *(const float4*)&vrow[0];
            float4 v1 = *(const float4*)&vrow[4];
            float4 v2 = *(const float4*)&vrow[8];
            float4 v3 = *(const float4*)&vrow[12];
            acc[0]  = fmaf(pj, v0.x, acc[0]);
            acc[1]  = fmaf(pj, v0.y, acc[1]);
            acc[2]  = fmaf(pj, v0.z, acc[2]);
            acc[3]  = fmaf(pj, v0.w, acc[3]);
            acc[4]  = fmaf(pj, v1.x, acc[4]);
            acc[5]  = fmaf(pj, v1.y, acc[5]);
            acc[6]  = fmaf(pj, v1.z, acc[6]);
            acc[7]  = fmaf(pj, v1.w, acc[7]);
            acc[8]  = fmaf(pj, v2.x, acc[8]);
            acc[9]  = fmaf(pj, v2.y, acc[9]);
            acc[10] = fmaf(pj, v2.z, acc[10]);
            acc[11] = fmaf(pj, v2.w, acc[11]);
            acc[12] = fmaf(pj, v3.x, acc[12]);
            acc[13] = fmaf(pj, v3.y, acc[13]);
            acc[14] = fmaf(pj, v3.z, acc[14]);
            acc[15] = fmaf(pj, v3.w, acc[15]);
        }
    }

    const float inv = 1.f / l;
    float* orow = O + base + (size_t)(qt * 64 + r) * Dd + cg;
    #pragma unroll
    for (int c = 0; c < 4; c++) {
        float4 o;
        o.x = acc[c * 4 + 0] * inv;
        o.y = acc[c * 4 + 1] * inv;
        o.z = acc[c * 4 + 2] * inv;
        o.w = acc[c * 4 + 3] * inv;
        *(float4*)&orow[c * 4] = o;
    }
}

// ----------------------------------------------------------------------------
// Fused residual + LayerNorm: out[row] = LN(A[row] + Badd[row]) * g + b
// One block (256 threads) per row of 768. Biased variance, eps = 1e-5.
// ----------------------------------------------------------------------------
__global__ void __launch_bounds__(256) ln_kernel(
    const float* __restrict__ A, const float* __restrict__ Badd,
    const float* __restrict__ gw, const float* __restrict__ bw,
    float* __restrict__ out)
{
    __shared__ float red[64];
    __shared__ float smu, sinv;
    const size_t row = blockIdx.x;
    const int t = threadIdx.x;
    const size_t off = row * Dd;

    float v0 = A[off + t]       + Badd[off + t];
    float v1 = A[off + 256 + t] + Badd[off + 256 + t];
    float v2 = A[off + 512 + t] + Badd[off + 512 + t];

    float s  = v0 + v1 + v2;
    float s2 = v0 * v0 + v1 * v1 + v2 * v2;
    #pragma unroll
    for (int o = 16; o; o >>= 1) {
        s  += __shfl_xor_sync(0xffffffffu, s, o);
        s2 += __shfl_xor_sync(0xffffffffu, s2, o);
    }
    const int w = t >> 5;
    if ((t & 31) == 0) { red[w] = s; red[w + 32] = s2; }
    __syncthreads();
    if (t == 0) {
        float S = 0.f, S2 = 0.f;
        #pragma unroll
        for (int i = 0; i < 8; i++) { S += red[i]; S2 += red[i + 32]; }
        float mu  = S * (1.f / 768.f);
        float var = S2 * (1.f / 768.f) - mu * mu;
        smu  = mu;
        sinv = rsqrtf(var + 1e-5f);
    }
    __syncthreads();
    const float mu = smu, inv = sinv;
    out[off + t]       = (v0 - mu) * inv * gw[t]       + bw[t];
    out[off + 256 + t] = (v1 - mu) * inv * gw[t + 256] + bw[t + 256];
    out[off + 512 + t] = (v2 - mu) * inv * gw[t + 512] + bw[t + 512];
}

// ----------------------------------------------------------------------------
// Host launcher
// Inputs (metadata order): x, attn_mask, Wq, Wk, Wv, Wo, bo, ln1_g, ln1_b,
//                          W1, b1, W2, b2, ln2_g, ln2_b
// attn_mask (d_in[1]) is the fixed causal mask; handled analytically.
// ----------------------------------------------------------------------------
extern "C" void kernel_launch(void* const* d_in, const int* in_sizes, int n_in,
                              void* d_out, int out_size)
{
    (void)in_sizes; (void)n_in; (void)out_size;

    const float* x     = (const float*)d_in[0];
    const float* Wq    = (const float*)d_in[2];
    const float* Wk    = (const float*)d_in[3];
    const float* Wv    = (const float*)d_in[4];
    const float* Wo    = (const float*)d_in[5];
    const float* bo    = (const float*)d_in[6];
    const float* ln1_g = (const float*)d_in[7];
    const float* ln1_b = (const float*)d_in[8];
    const float* W1    = (const float*)d_in[9];
    const float* b1    = (const float*)d_in[10];
    const float* W2    = (const float*)d_in[11];
    const float* b2    = (const float*)d_in[12];
    const float* ln2_g = (const float*)d_in[13];
    const float* ln2_b = (const float*)d_in[14];

    float *px, *pq, *pk, *pv, *pattn, *pmid;
    cudaGetSymbolAddress((void**)&px,    g_x);
    cudaGetSymbolAddress((void**)&pq,    g_q);
    cudaGetSymbolAddress((void**)&pk,    g_k);
    cudaGetSymbolAddress((void**)&pv,    g_v);
    cudaGetSymbolAddress((void**)&pattn, g_attn);
    cudaGetSymbolAddress((void**)&pmid,  g_mid);

    cudaFuncSetAttribute(flash_attn_kernel,
                         cudaFuncAttributeMaxDynamicSharedMemorySize, FLASH_SMEM);

    const dim3 blk(256);
    const dim3 gD(Dd / 64, Mrows / 64);   // N=768 GEMMs
    const dim3 gF(Ff / 64, Mrows / 64);   // N=3072 GEMM
    const dim3 gA(Ss / 64, Bb * Hh);      // flash attention

    const float* cur_x = x;
    for (int l = 0; l < Ll; l++) {
        const float* Wq_l = Wq + (size_t)l * Dd * Dd;
        const float* Wk_l = Wk + (size_t)l * Dd * Dd;
        const float* Wv_l = Wv + (size_t)l * Dd * Dd;
        const float* Wo_l = Wo + (size_t)l * Dd * Dd;
        const float* bo_l = bo + (size_t)l * Dd;
        const float* g1_l = ln1_g + (size_t)l * Dd;
        const float* c1_l = ln1_b + (size_t)l * Dd;
        const float* W1_l = W1 + (size_t)l * Dd * Ff;
        const float* b1_l = b1 + (size_t)l * Ff;
        const float* W2_l = W2 + (size_t)l * Ff * Dd;
        const float* b2_l = b2 + (size_t)l * Dd;
        const float* g2_l = ln2_g + (size_t)l * Dd;
        const float* c2_l = ln2_b + (size_t)l * Dd;

        // QKV projections
        sgemm_kernel<0><<<gD, blk>>>(cur_x, Wq_l, nullptr, pq, Mrows, Dd, Dd);
        sgemm_kernel<0><<<gD, blk>>>(cur_x, Wk_l, nullptr, pk, Mrows, Dd, Dd);
        sgemm_kernel<0><<<gD, blk>>>(cur_x, Wv_l, nullptr, pv, Mrows, Dd, Dd);

        // causal flash attention -> merged av in g_attn
        flash_attn_kernel<<<gA, blk, FLASH_SMEM>>>(pq, pk, pv, pattn);

        // attn_out = av @ Wo + bo  (into pq, q is dead)
        sgemm_kernel<0><<<gD, blk>>>(pattn, Wo_l, bo_l, pq, Mrows, Dd, Dd);

        // h = LN(x + attn_out)
        ln_kernel<<<Mrows, blk>>>(cur_x, pq, g1_l, c1_l, px);

        // mid = gelu(h @ W1 + b1)
        sgemm_kernel<1><<<gF, blk>>>(px, W1_l, b1_l, pmid, Mrows, Ff, Dd);

        // f = mid @ W2 + b2  (into pattn)
        sgemm_kernel<0><<<gD, blk>>>(pmid, W2_l, b2_l, pattn, Mrows, Dd, Ff);

        // x_next = LN(h + f); last layer writes d_out
        float* dst = (l == Ll - 1) ? (float*)d_out : px;
        ln_kernel<<<Mrows, blk>>>(px, pattn, g2_l, c2_l, dst);

        cur_x = px;
    }
}

// round 3
// speedup vs baseline: 1.5690x; 1.5690x over previous
#include <cuda_runtime.h>
#include <cuda_bf16.h>
#include <math.h>
#include <stdint.h>

// Problem constants
#define Bb 4
#define Ss 2048
#define Dd 768
#define Hh 12
#define Ff 3072
#define Ll 4
#define DHh 64
#define Mrows (Bb*Ss)   // 8192

// ---------------------------------------------------------------------------
// Scratch (device globals; allocation is forbidden)
// ---------------------------------------------------------------------------
__device__ float g_x[Bb*Ss*Dd];     // running activations (h)
__device__ float g_q[Bb*Ss*Dd];     // q / attn_out scratch
__device__ float g_k[Bb*Ss*Dd];
__device__ float g_v[Bb*Ss*Dd];
__device__ float g_attn[Bb*Ss*Dd];  // av merged / ffn out
__device__ float g_mid[Bb*Ss*Ff];   // ffn intermediate

// Preprocessed (transposed [N,K] K-major, bf16 hi/lo split) weights
__device__ __nv_bfloat16 g_wqkv_h[Ll*3*Dd*Dd];
__device__ __nv_bfloat16 g_wqkv_l[Ll*3*Dd*Dd];
__device__ __nv_bfloat16 g_wo_h[Ll*Dd*Dd];
__device__ __nv_bfloat16 g_wo_l[Ll*Dd*Dd];
__device__ __nv_bfloat16 g_w1_h[Ll*Ff*Dd];
__device__ __nv_bfloat16 g_w1_l[Ll*Ff*Dd];
__device__ __nv_bfloat16 g_w2_h[Ll*Dd*Ff];
__device__ __nv_bfloat16 g_w2_l[Ll*Dd*Ff];

__device__ __forceinline__ float gelu_exact(float v) {
    return 0.5f * v * (1.0f + erff(v * 0.70710678118654752f));
}

__device__ __forceinline__ void mma16816(float* c, const uint32_t* a,
                                         const uint32_t* b) {
    asm volatile(
        "mma.sync.aligned.m16n8k16.row.col.f32.bf16.bf16.f32 "
        "{%0,%1,%2,%3}, {%4,%5,%6,%7}, {%8,%9}, {%0,%1,%2,%3};"
        : "+f"(c[0]), "+f"(c[1]), "+f"(c[2]), "+f"(c[3])
        : "r"(a[0]), "r"(a[1]), "r"(a[2]), "r"(a[3]), "r"(b[0]), "r"(b[1]));
}

__device__ __forceinline__ uint32_t pack_bf2(__nv_bfloat16 a, __nv_bfloat16 b) {
    __nv_bfloat162 p; p.x = a; p.y = b;
    return *(uint32_t*)&p;
}

__device__ __forceinline__ void split2(float x, float y,
                                       uint32_t& h, uint32_t& l) {
    __nv_bfloat16 hx = __float2bfloat16(x);
    __nv_bfloat16 hy = __float2bfloat16(y);
    __nv_bfloat16 lx = __float2bfloat16(x - __bfloat162float(hx));
    __nv_bfloat16 ly = __float2bfloat16(y - __bfloat162float(hy));
    h = pack_bf2(hx, hy);
    l = pack_bf2(lx, ly);
}

// ---------------------------------------------------------------------------
// Weight preprocessing: out[n][k] = W[k][n] as bf16 hi + bf16 lo.
// ---------------------------------------------------------------------------
__global__ void __launch_bounds__(256) transpose_split_kernel(
    const float* __restrict__ W, __nv_bfloat16* __restrict__ oh,
    __nv_bfloat16* __restrict__ ol, int K, int N, int rowOff,
    size_t inLS, size_t outLS)
{
    __shared__ float tile[32][33];
    const float* Wl = W + (size_t)blockIdx.z * inLS;
    __nv_bfloat16* ohl = oh + (size_t)blockIdx.z * outLS;
    __nv_bfloat16* oll = ol + (size_t)blockIdx.z * outLS;
    const int nb = blockIdx.x * 32, kb = blockIdx.y * 32;
    const int tx = threadIdx.x, ty = threadIdx.y;
    #pragma unroll
    for (int j = 0; j < 32; j += 8)
        tile[ty + j][tx] = Wl[(size_t)(kb + ty + j) * N + nb + tx];
    __syncthreads();
    #pragma unroll
    for (int j = 0; j < 32; j += 8) {
        float v = tile[tx][ty + j];
        int n = nb + ty + j, k = kb + tx;
        __nv_bfloat16 h  = __float2bfloat16(v);
        __nv_bfloat16 lo = __float2bfloat16(v - __bfloat162float(h));
        ohl[(size_t)(rowOff + n) * K + k] = h;
        oll[(size_t)(rowOff + n) * K + k] = lo;
    }
}

// ---------------------------------------------------------------------------
// Tensor-core GEMM via mma.sync (base-target safe).
// C[M,N] = A[M,K](fp32) @ Wt[N,K]^T, 3-term bf16 split, fp32 accum.
// CTA tile 128x128, BK=32, 8 warps (each 32 rows x 64 cols).
// mode: 0 = +bias, 1 = +bias +exact GELU, 2 = QKV split (768-col outputs).
// ---------------------------------------------------------------------------
#define BKP 40                       // padded K ld (elements) -> 80B rows
#define TILE_E (128 * BKP)           // elements per tile buffer
#define STAGE_E (4 * TILE_E)         // Ah, Al, Wh, Wl
#define GEMM_SMEM (2 * STAGE_E * 2)  // bytes (bf16), 2 stages = 81920

__global__ void __launch_bounds__(256, 1)
tc_gemm_kernel(const float* __restrict__ A,
               const __nv_bfloat16* __restrict__ Wh,
               const __nv_bfloat16* __restrict__ Wl,
               const float* __restrict__ bias,
               float* __restrict__ C0, float* __restrict__ C1,
               float* __restrict__ C2,
               int N, int K, int mode)
{
    extern __shared__ __nv_bfloat16 sm[];
    const int t   = threadIdx.x;
    const int wid = t >> 5, l = t & 31;
    const int wm  = wid & 3;          // m block (32 rows)
    const int wn  = wid >> 2;         // n block (64 cols)
    const int n0  = blockIdx.x * 128;
    const int m0  = blockIdx.y * 128;

    const float* Ab = A + (size_t)m0 * K;
    const __nv_bfloat16* Whb = Wh + (size_t)n0 * K;
    const __nv_bfloat16* Wlb = Wl + (size_t)n0 * K;

    // Per-thread load indices
    const int a_row = t >> 3;             // +32 per p (4 ldgs)
    const int a_kq  = (t & 7) * 4;
    const int w_row = t >> 2;             // +64 per p (2 ldgs)
    const int w_kq  = (t & 3) * 8;

    float acc[2][8][4];
    #pragma unroll
    for (int m = 0; m < 2; m++)
        #pragma unroll
        for (int n = 0; n < 8; n++)
            #pragma unroll
            for (int e = 0; e < 4; e++) acc[m][n][e] = 0.f;

    const int nIter = K >> 5;

    float4 aR[4];
    uint4  whR[2], wlR[2];

    // Prologue: load tile 0
    #pragma unroll
    for (int p = 0; p < 4; p++)
        aR[p] = *(const float4*)(Ab + (size_t)(a_row + p * 32) * K + a_kq);
    #pragma unroll
    for (int p = 0; p < 2; p++) {
        whR[p] = *(const uint4*)(Whb + (size_t)(w_row + p * 64) * K + w_kq);
        wlR[p] = *(const uint4*)(Wlb + (size_t)(w_row + p * 64) * K + w_kq);
    }
    // STS tile 0 -> stage 0
    {
        __nv_bfloat16* sAh = sm;
        __nv_bfloat16* sAl = sm + TILE_E;
        __nv_bfloat16* sWh = sm + 2 * TILE_E;
        __nv_bfloat16* sWl = sm + 3 * TILE_E;
        #pragma unroll
        for (int p = 0; p < 4; p++) {
            uint32_t h0, l0, h1, l1;
            split2(aR[p].x, aR[p].y, h0, l0);
            split2(aR[p].z, aR[p].w, h1, l1);
            int off = (a_row + p * 32) * BKP + a_kq;
            *(uint2*)&sAh[off] = make_uint2(h0, h1);
            *(uint2*)&sAl[off] = make_uint2(l0, l1);
        }
        #pragma unroll
        for (int p = 0; p < 2; p++) {
            int off = (w_row + p * 64) * BKP + w_kq;
            *(uint4*)&sWh[off] = whR[p];
            *(uint4*)&sWl[off] = wlR[p];
        }
    }
    __syncthreads();

    for (int it = 0; it < nIter; it++) {
        const int cur = it & 1;
        const bool more = (it + 1 < nIter);
        if (more) {
            const int kt = (it + 1) << 5;
            #pragma unroll
            for (int p = 0; p < 4; p++)
                aR[p] = *(const float4*)(Ab + (size_t)(a_row + p * 32) * K + kt + a_kq);
            #pragma unroll
            for (int p = 0; p < 2; p++) {
                whR[p] = *(const uint4*)(Whb + (size_t)(w_row + p * 64) * K + kt + w_kq);
                wlR[p] = *(const uint4*)(Wlb + (size_t)(w_row + p * 64) * K + kt + w_kq);
            }
        }

        // Compute on stage cur
        {
            const __nv_bfloat16* sAh = sm + cur * STAGE_E;
            const __nv_bfloat16* sAl = sAh + TILE_E;
            const __nv_bfloat16* sWh = sAh + 2 * TILE_E;
            const __nv_bfloat16* sWl = sAh + 3 * TILE_E;
            #pragma unroll
            for (int ks = 0; ks < 2; ks++) {
                const int k0 = ks * 16;
                uint32_t ah[2][4], al[2][4];
                #pragma unroll
                for (int m = 0; m < 2; m++) {
                    int r0 = wm * 32 + m * 16 + (l >> 2);
                    int cc = k0 + (l & 3) * 2;
                    ah[m][0] = *(const uint32_t*)&sAh[r0 * BKP + cc];
                    ah[m][1] = *(const uint32_t*)&sAh[(r0 + 8) * BKP + cc];
                    ah[m][2] = *(const uint32_t*)&sAh[r0 * BKP + cc + 8];
                    ah[m][3] = *(const uint32_t*)&sAh[(r0 + 8) * BKP + cc + 8];
                    al[m][0] = *(const uint32_t*)&sAl[r0 * BKP + cc];
                    al[m][1] = *(const uint32_t*)&sAl[(r0 + 8) * BKP + cc];
                    al[m][2] = *(const uint32_t*)&sAl[r0 * BKP + cc + 8];
                    al[m][3] = *(const uint32_t*)&sAl[(r0 + 8) * BKP + cc + 8];
                }
                #pragma unroll
                for (int n = 0; n < 8; n++) {
                    int col = wn * 64 + n * 8 + (l >> 2);
                    int kk  = k0 + (l & 3) * 2;
                    uint32_t bh[2], bl[2];
                    bh[0] = *(const uint32_t*)&sWh[col * BKP + kk];
                    bh[1] = *(const uint32_t*)&sWh[col * BKP + kk + 8];
                    bl[0] = *(const uint32_t*)&sWl[col * BKP + kk];
                    bl[1] = *(const uint32_t*)&sWl[col * BKP + kk + 8];
                    #pragma unroll
                    for (int m = 0; m < 2; m++) {
                        mma16816(acc[m][n], ah[m], bh);
                        mma16816(acc[m][n], al[m], bh);
                        mma16816(acc[m][n], ah[m], bl);
                    }
                }
            }
        }

        if (more) {
            __nv_bfloat16* sAh = sm + (cur ^ 1) * STAGE_E;
            __nv_bfloat16* sAl = sAh + TILE_E;
            __nv_bfloat16* sWh = sAh + 2 * TILE_E;
            __nv_bfloat16* sWl = sAh + 3 * TILE_E;
            #pragma unroll
            for (int p = 0; p < 4; p++) {
                uint32_t h0, l0, h1, l1;
                split2(aR[p].x, aR[p].y, h0, l0);
                split2(aR[p].z, aR[p].w, h1, l1);
                int off = (a_row + p * 32) * BKP + a_kq;
                *(uint2*)&sAh[off] = make_uint2(h0, h1);
                *(uint2*)&sAl[off] = make_uint2(l0, l1);
            }
            #pragma unroll
            for (int p = 0; p < 2; p++) {
                int off = (w_row + p * 64) * BKP + w_kq;
                *(uint4*)&sWh[off] = whR[p];
                *(uint4*)&sWl[off] = wlR[p];
            }
        }
        __syncthreads();
    }

    // Epilogue
    float* dst; int nbase; size_t Nout;
    if (mode == 2) {
        int which = n0 / 768;
        dst = (which == 0) ? C0 : ((which == 1) ? C1 : C2);
        nbase = n0 % 768;
        Nout = 768;
    } else {
        dst = C0; nbase = n0; Nout = (size_t)N;
    }
    const int rbase = m0 + wm * 32 + (l >> 2);
    #pragma unroll
    for (int m = 0; m < 2; m++) {
        #pragma unroll
        for (int n = 0; n < 8; n++) {
            int colA = n0 + wn * 64 + n * 8 + (l & 3) * 2;    // bias index
            int colC = nbase + wn * 64 + n * 8 + (l & 3) * 2; // store index
            float b0 = bias ? bias[colA]     : 0.f;
            float b1 = bias ? bias[colA + 1] : 0.f;
            float v0 = acc[m][n][0] + b0;
            float v1 = acc[m][n][1] + b1;
            float v2 = acc[m][n][2] + b0;
            float v3 = acc[m][n][3] + b1;
            if (mode == 1) {
                v0 = gelu_exact(v0); v1 = gelu_exact(v1);
                v2 = gelu_exact(v2); v3 = gelu_exact(v3);
            }
            size_t r0 = (size_t)(rbase + m * 16) * Nout + colC;
            size_t r1 = (size_t)(rbase + m * 16 + 8) * Nout + colC;
            *(float2*)&dst[r0] = make_float2(v0, v1);
            *(float2*)&dst[r1] = make_float2(v2, v3);
        }
    }
}

// ----------------------------------------------------------------------------
// Flash attention (causal), fp32, one 64-row Q tile per block, 256 threads.
// ----------------------------------------------------------------------------
#define FLASH_LD 68
#define FLASH_SMEM (3 * 64 * FLASH_LD * 4)

__global__ void __launch_bounds__(256) flash_attn_kernel(
    const float* __restrict__ Q, const float* __restrict__ Kt,
    const float* __restrict__ Vt, float* __restrict__ O)
{
    extern __shared__ float smf[];
    float* Qs = smf;
    float* Ks = smf + 64 * FLASH_LD;
    float* Vs = smf + 2 * 64 * FLASH_LD;

    const int qt = blockIdx.x;
    const int bh = blockIdx.y;
    const int b  = bh / Hh;
    const int h  = bh % Hh;
    const int t  = threadIdx.x;
    const int r  = t >> 2;
    const int kq = t & 3;
    const int cg = (t & 3) * 16;

    const size_t base = (size_t)b * Ss * Dd + (size_t)h * DHh;

    for (int idx = t; idx < 64 * 16; idx += 256) {
        int i  = idx >> 4;
        int dq = (idx & 15) * 4;
        *(float4*)&Qs[i * FLASH_LD + dq] =
            *(const float4*)(Q + base + (size_t)(qt * 64 + i) * Dd + dq);
    }

    float m = -1e30f, l = 0.f;
    float acc[16];
    #pragma unroll
    for (int i = 0; i < 16; i++) acc[i] = 0.f;

    for (int jt = 0; jt <= qt; jt++) {
        __syncthreads();
        for (int idx = t; idx < 64 * 16; idx += 256) {
            int i  = idx >> 4;
            int dq = (idx & 15) * 4;
            *(float4*)&Ks[i * FLASH_LD + dq] =
                *(const float4*)(Kt + base + (size_t)(jt * 64 + i) * Dd + dq);
            *(float4*)&Vs[i * FLASH_LD + dq] =
                *(const float4*)(Vt + base + (size_t)(jt * 64 + i) * Dd + dq);
        }
        __syncthreads();

        float s[16];
        #pragma unroll
        for (int kk = 0; kk < 16; kk++) s[kk] = 0.f;
        #pragma unroll 4
        for (int d4 = 0; d4 < 64; d4 += 4) {
            float4 q4 = *(const float4*)&Qs[r * FLASH_LD + d4];
            #pragma unroll
            for (int kk = 0; kk < 16; kk++) {
                float4 k4 = *(const float4*)&Ks[(kq + 4 * kk) * FLASH_LD + d4];
                s[kk] = fmaf(q4.x, k4.x,
                        fmaf(q4.y, k4.y,
                        fmaf(q4.z, k4.z,
                        fmaf(q4.w, k4.w, s[kk]))));
            }
        }

        float mloc = -1e30f;
        const bool diag = (jt == qt);
        #pragma unroll
        for (int kk = 0; kk < 16; kk++) {
            float sv = s[kk] * 0.125f;
            if (diag && (kq + 4 * kk) > r) sv = -1e9f;
            s[kk] = sv;
            mloc = fmaxf(mloc, sv);
        }
        mloc = fmaxf(mloc, __shfl_xor_sync(0xffffffffu, mloc, 1));
        mloc = fmaxf(mloc, __shfl_xor_sync(0xffffffffu, mloc, 2));

        const float mnew  = fmaxf(m, mloc);
        const float scale = __expf(m - mnew);

        float lloc = 0.f;
        #pragma unroll
        for (int kk = 0; kk < 16; kk++) {
            s[kk] = __expf(s[kk] - mnew);
            lloc += s[kk];
        }
        lloc += __shfl_xor_sync(0xffffffffu, lloc, 1);
        lloc += __shfl_xor_sync(0xffffffffu, lloc, 2);
        l = l * scale + lloc;
        m = mnew;
        #pragma unroll
        for (int i = 0; i < 16; i++) acc[i] *= scale;

        __syncthreads();
        #pragma unroll
        for (int kk = 0; kk < 16; kk++)
            Ks[r * FLASH_LD + kq + 4 * kk] = s[kk];
        __syncthreads();

        #pragma unroll 8
        for (int j = 0; j < 64; j++) {
            float pj = Ks[r * FLASH_LD + j];
            const float* vrow = &Vs[j * FLASH_LD + cg];
            float4 v0 = *(const float4*)&vrow[0];
            float4 v1 = *(const float4*)&vrow[4];
            float4 v2 = *(const float4*)&vrow[8];
            float4 v3 = *(const float4*)&vrow[12];
            acc[0]  = fmaf(pj, v0.x, acc[0]);
            acc[1]  = fmaf(pj, v0.y, acc[1]);
            acc[2]  = fmaf(pj, v0.z, acc[2]);
            acc[3]  = fmaf(pj, v0.w, acc[3]);
            acc[4]  = fmaf(pj, v1.x, acc[4]);
            acc[5]  = fmaf(pj, v1.y, acc[5]);
            acc[6]  = fmaf(pj, v1.z, acc[6]);
            acc[7]  = fmaf(pj, v1.w, acc[7]);
            acc[8]  = fmaf(pj, v2.x, acc[8]);
            acc[9]  = fmaf(pj, v2.y, acc[9]);
            acc[10] = fmaf(pj, v2.z, acc[10]);
            acc[11] = fmaf(pj, v2.w, acc[11]);
            acc[12] = fmaf(pj, v3.x, acc[12]);
            acc[13] = fmaf(pj, v3.y, acc[13]);
            acc[14] = fmaf(pj, v3.z, acc[14]);
            acc[15] = fmaf(pj, v3.w, acc[15]);
        }
    }

    const float inv = 1.f / l;
    float* orow = O + base + (size_t)(qt * 64 + r) * Dd + cg;
    #pragma unroll
    for (int c = 0; c < 4; c++) {
        float4 o;
        o.x = acc[c * 4 + 0] * inv;
        o.y = acc[c * 4 + 1] * inv;
        o.z = acc[c * 4 + 2] * inv;
        o.w = acc[c * 4 + 3] * inv;
        *(float4*)&orow[c * 4] = o;
    }
}

// ----------------------------------------------------------------------------
// Fused residual + LayerNorm
// ----------------------------------------------------------------------------
__global__ void __launch_bounds__(256) ln_kernel(
    const float* __restrict__ A, const float* __restrict__ Badd,
    const float* __restrict__ gw, const float* __restrict__ bw,
    float* __restrict__ out)
{
    __shared__ float red[64];
    __shared__ float smu, sinv;
    const size_t row = blockIdx.x;
    const int t = threadIdx.x;
    const size_t off = row * Dd;

    float v0 = A[off + t]       + Badd[off + t];
    float v1 = A[off + 256 + t] + Badd[off + 256 + t];
    float v2 = A[off + 512 + t] + Badd[off + 512 + t];

    float s  = v0 + v1 + v2;
    float s2 = v0 * v0 + v1 * v1 + v2 * v2;
    #pragma unroll
    for (int o = 16; o; o >>= 1) {
        s  += __shfl_xor_sync(0xffffffffu, s, o);
        s2 += __shfl_xor_sync(0xffffffffu, s2, o);
    }
    const int w = t >> 5;
    if ((t & 31) == 0) { red[w] = s; red[w + 32] = s2; }
    __syncthreads();
    if (t == 0) {
        float S = 0.f, S2 = 0.f;
        #pragma unroll
        for (int i = 0; i < 8; i++) { S += red[i]; S2 += red[i + 32]; }
        float mu  = S * (1.f / 768.f);
        float var = S2 * (1.f / 768.f) - mu * mu;
        smu  = mu;
        sinv = rsqrtf(var + 1e-5f);
    }
    __syncthreads();
    const float mu = smu, inv = sinv;
    out[off + t]       = (v0 - mu) * inv * gw[t]       + bw[t];
    out[off + 256 + t] = (v1 - mu) * inv * gw[t + 256] + bw[t + 256];
    out[off + 512 + t] = (v2 - mu) * inv * gw[t + 512] + bw[t + 512];
}

// ----------------------------------------------------------------------------
// Host launcher
// ----------------------------------------------------------------------------
extern "C" void kernel_launch(void* const* d_in, const int* in_sizes, int n_in,
                              void* d_out, int out_size)
{
    (void)in_sizes; (void)n_in; (void)out_size;

    const float* x     = (const float*)d_in[0];
    const float* Wq    = (const float*)d_in[2];
    const float* Wk    = (const float*)d_in[3];
    const float* Wv    = (const float*)d_in[4];
    const float* Wo    = (const float*)d_in[5];
    const float* bo    = (const float*)d_in[6];
    const float* ln1_g = (const float*)d_in[7];
    const float* ln1_b = (const float*)d_in[8];
    const float* W1    = (const float*)d_in[9];
    const float* b1    = (const float*)d_in[10];
    const float* W2    = (const float*)d_in[11];
    const float* b2    = (const float*)d_in[12];
    const float* ln2_g = (const float*)d_in[13];
    const float* ln2_b = (const float*)d_in[14];

    float *px, *pq, *pk, *pv, *pattn, *pmid;
    cudaGetSymbolAddress((void**)&px,    g_x);
    cudaGetSymbolAddress((void**)&pq,    g_q);
    cudaGetSymbolAddress((void**)&pk,    g_k);
    cudaGetSymbolAddress((void**)&pv,    g_v);
    cudaGetSymbolAddress((void**)&pattn, g_attn);
    cudaGetSymbolAddress((void**)&pmid,  g_mid);

    __nv_bfloat16 *qkvh, *qkvl, *woh, *wol, *w1h, *w1l, *w2h, *w2l;
    cudaGetSymbolAddress((void**)&qkvh, g_wqkv_h);
    cudaGetSymbolAddress((void**)&qkvl, g_wqkv_l);
    cudaGetSymbolAddress((void**)&woh,  g_wo_h);
    cudaGetSymbolAddress((void**)&wol,  g_wo_l);
    cudaGetSymbolAddress((void**)&w1h,  g_w1_h);
    cudaGetSymbolAddress((void**)&w1l,  g_w1_l);
    cudaGetSymbolAddress((void**)&w2h,  g_w2_h);
    cudaGetSymbolAddress((void**)&w2l,  g_w2_l);

    cudaFuncSetAttribute(flash_attn_kernel,
                         cudaFuncAttributeMaxDynamicSharedMemorySize, FLASH_SMEM);
    cudaFuncSetAttribute(tc_gemm_kernel,
                         cudaFuncAttributeMaxDynamicSharedMemorySize, GEMM_SMEM);

    const size_t DD = (size_t)Dd * Dd;
    const size_t DF = (size_t)Dd * Ff;

    // Preprocess weights: transpose to [N,K] + bf16 hi/lo split, all layers.
    {
        dim3 tb(32, 8);
        transpose_split_kernel<<<dim3(Dd/32, Dd/32, Ll), tb>>>(
            Wq, qkvh, qkvl, Dd, Dd, 0,    DD, 3 * DD);
        transpose_split_kernel<<<dim3(Dd/32, Dd/32, Ll), tb>>>(
            Wk, qkvh, qkvl, Dd, Dd, 768,  DD, 3 * DD);
        transpose_split_kernel<<<dim3(Dd/32, Dd/32, Ll), tb>>>(
            Wv, qkvh, qkvl, Dd, Dd, 1536, DD, 3 * DD);
        transpose_split_kernel<<<dim3(Dd/32, Dd/32, Ll), tb>>>(
            Wo, woh, wol, Dd, Dd, 0, DD, DD);
        transpose_split_kernel<<<dim3(Ff/32, Dd/32, Ll), tb>>>(
            W1, w1h, w1l, Dd, Ff, 0, DF, DF);
        transpose_split_kernel<<<dim3(Dd/32, Ff/32, Ll), tb>>>(
            W2, w2h, w2l, Ff, Dd, 0, DF, DF);
    }

    const dim3 blk(256);
    const dim3 gA(Ss / 64, Bb * Hh);

    const float* cur_x = x;
    for (int l = 0; l < Ll; l++) {
        const float* bo_l = bo + (size_t)l * Dd;
        const float* g1_l = ln1_g + (size_t)l * Dd;
        const float* c1_l = ln1_b + (size_t)l * Dd;
        const float* b1_l = b1 + (size_t)l * Ff;
        const float* b2_l = b2 + (size_t)l * Dd;
        const float* g2_l = ln2_g + (size_t)l * Dd;
        const float* c2_l = ln2_b + (size_t)l * Dd;

        // Fused QKV: N=2304, epilogue routes to q/k/v
        tc_gemm_kernel<<<dim3(18, 64), blk, GEMM_SMEM>>>(
            cur_x, qkvh + l * 3 * DD, qkvl + l * 3 * DD, nullptr,
            pq, pk, pv, 2304, 768, 2);

        // causal flash attention -> merged av in g_attn
        flash_attn_kernel<<<gA, blk, FLASH_SMEM>>>(pq, pk, pv, pattn);

        // attn_out = av @ Wo + bo  (into pq)
        tc_gemm_kernel<<<dim3(6, 64), blk, GEMM_SMEM>>>(
            pattn, woh + l * DD, wol + l * DD, bo_l,
            pq, pq, pq, 768, 768, 0);

        // h = LN(x + attn_out)
        ln_kernel<<<Mrows, blk>>>(cur_x, pq, g1_l, c1_l, px);

        // mid = gelu(h @ W1 + b1)
        tc_gemm_kernel<<<dim3(24, 64), blk, GEMM_SMEM>>>(
            px, w1h + l * DF, w1l + l * DF, b1_l,
            pmid, pmid, pmid, 3072, 768, 1);

        // f = mid @ W2 + b2  (into pattn)
        tc_gemm_kernel<<<dim3(6, 64), blk, GEMM_SMEM>>>(
            pmid, w2h + l * DF, w2l + l * DF, b2_l,
            pattn, pattn, pattn, 768, 3072, 0);

        // x_next = LN(h + f); last layer writes d_out
        float* dst = (l == Ll - 1) ? (float*)d_out : px;
        ln_kernel<<<Mrows, blk>>>(px, pattn, g2_l, c2_l, dst);

        cur_x = px;
    }
}